// round 14
// baseline (speedup 1.0000x reference)
#include <cuda_runtime.h>
#include <cuda_fp16.h>

#define NBANDS 100
#define TT 19
#define FFb 513
#define BB 256
#define KTOT 528          // 400 feat + 128 h (= 33 k-tiles of 16)
#define GC 512            // gate columns: rz(256) | i_n(128) | h_n(128)
#define WINLEN 842
#define FSAMP 16000
#define RPB 2             // batch rows per block
#define NBLK (BB/RPB)     // 128 blocks
#define NTHR 1024
#define NKT 33            // k-tiles
#define WB_UINTS (32*NKT*32*4)   // B-fragment weight layout, 135168 uints

// ---------------- device state / scratch ----------------
__device__ float d_fc[NBANDS], d_q0[NBANDS], d_dq[NBANDS];
__device__ __align__(16) unsigned d_Wb[WB_UINTS];  // mma B-frags: [warp][ktile][lane][4]
__device__ float d_biasc[GC];
__device__ __align__(16) float2 d_mag[BB*TT*FFb];  // (|L|,|R|)

// ---------------- constants (ERB scale) ----------------
__global__ void k_consts() {
    int n = threadIdx.x;
    if (n < NBANDS) {
        double E0 = 21.4 * log10(4.37 * 50.0   / 1000.0 + 1.0);
        double E1 = 21.4 * log10(4.37 * 7200.0 / 1000.0 + 1.0);
        double E  = E0 + (E1 - E0) * ((double)n / 99.0);
        double fc = (pow(10.0, E / 21.4) - 1.0) * 1000.0 / 4.37;
        double erb = 24.7 * (4.37 * fc / 1000.0 + 1.0);
        double q0 = fc / (1.019 * erb);
        double En = (E - E0) / (E1 - E0 + 1e-12);
        double dq = 2.0 * (0.5 + 0.5 * En);
        if (dq < 0.001) dq = 0.001;
        d_fc[n] = (float)fc; d_q0[n] = (float)q0; d_dq[n] = (float)dq;
    }
}

__device__ __forceinline__ float wcomb(const float* w_ih, const float* w_hh, int col, int k) {
    if (k >= KTOT) return 0.f;
    if (col < 256) return (k < 400) ? w_ih[col*400 + k] : w_hh[col*128 + (k-400)];
    if (col < 384) return (k < 400) ? w_ih[col*400 + k] : 0.f;
    return (k < 400) ? 0.f : w_hh[(col-128)*128 + (k-400)];
}

// Build mma B-fragment weight layout + bias.
// m16n8k16 .row.col B frag: lane l, reg r: half2 {B[kb][n], B[kb+1][n]},
//   kb = ktile*16 + (l%4)*2 + r*8,  n = l/4 within the 8-col n-tile.
// Packed so one LDG.128 per lane per ktile covers both n-tiles (j = ntile*2+reg).
__global__ void k_prep(const float* __restrict__ w_ih, const float* __restrict__ w_hh,
                       const float* __restrict__ b_ih, const float* __restrict__ b_hh) {
    int i = blockIdx.x * blockDim.x + threadIdx.x;
    if (i < WB_UINTS) {
        int tmp = i;
        int j    = tmp & 3;  tmp >>= 2;
        int lane = tmp & 31; tmp >>= 5;
        int kt   = tmp % NKT;
        int warp = tmp / NKT;
        int ntile = j >> 1, reg = j & 1;
        int n  = warp*16 + ntile*8 + (lane >> 2);
        int kb = kt*16 + (lane & 3)*2 + reg*8;
        float v0 = wcomb(w_ih, w_hh, n, kb);
        float v1 = wcomb(w_ih, w_hh, n, kb + 1);
        __half2 h = __floats2half2_rn(v0, v1);
        d_Wb[i] = *(unsigned*)&h;
        return;
    }
    int jj = i - WB_UINTS;
    if (jj < GC) {
        float v;
        if (jj < 256)      v = b_ih[jj] + b_hh[jj];
        else if (jj < 384) v = b_ih[jj];
        else               v = b_hh[jj - 128];
        d_biasc[jj] = v;
    }
}

// ---------------- packed L+iR 1024-pt FFT per (b,t), smem twiddles ----------------
__global__ void k_fft(const float* __restrict__ wavL, const float* __restrict__ wavR,
                      float* __restrict__ outXL, float* __restrict__ outXR,
                      int realmode, long long xl_off, long long xr_off, long long out_elems) {
    __shared__ float2 z[1024];
    __shared__ float2 twt[1023];
    int bt = blockIdx.x;
    int b = bt / TT, t = bt - b * TT;
    int tid = threadIdx.x;
    const float* wl = wavL + b * FSAMP + t * WINLEN;
    const float* wr = wavR + b * FSAMP + t * WINLEN;

    for (int g = tid; g < 1023; g += 256) {
        int hb = 31 - __clz(g + 1);
        int half = 1 << hb;
        int j = g + 1 - half;
        float s, c;
        __sincosf(-3.14159265358979f * (float)j / (float)half, &s, &c);
        twt[g] = make_float2(c, s);
    }
    for (int j = tid; j < 1024; j += 256) {
        float2 v = make_float2(0.f, 0.f);
        if (j < WINLEN) {
            float w = 0.5f - 0.5f * cosf(6.2831853071795864f * (float)j / (float)WINLEN);
            v.x = wl[j] * w; v.y = wr[j] * w;
        }
        z[__brev((unsigned)j) >> 22] = v;
    }
    __syncthreads();

    for (int len = 2; len <= 1024; len <<= 1) {
        int half = len >> 1;
        for (int i = tid; i < 512; i += 256) {
            int j = i & (half - 1);
            int base = ((i - j) << 1) + j;
            float2 w2 = twt[half - 1 + j];
            float c = w2.x, s = w2.y;
            float2 u = z[base], v = z[base + half];
            float tr = v.x * c - v.y * s;
            float ti = v.x * s + v.y * c;
            z[base]        = make_float2(u.x + tr, u.y + ti);
            z[base + half] = make_float2(u.x - tr, u.y - ti);
        }
        __syncthreads();
    }

    for (int k = tid; k < FFb; k += 256) {
        float2 zk = z[k];
        float2 zm = z[(1024 - k) & 1023];
        float lr = 0.5f * (zk.x + zm.x), li = 0.5f * (zk.y - zm.y);
        float rr = 0.5f * (zk.y + zm.y), ri = 0.5f * (zm.x - zk.x);
        long long o = (long long)bt * FFb + k;
        if (realmode) {
            outXL[o] = lr;
            outXR[o] = rr;
        } else {
            long long base2 = o * 2;
            if (xl_off + base2 + 1 < out_elems) {
                outXL[base2] = lr; outXL[base2 + 1] = li;
            }
            if (xr_off + base2 + 1 < out_elems) {
                outXR[base2] = rr; outXR[base2 + 1] = ri;
            }
        }
        d_mag[o] = make_float2(sqrtf(lr * lr + li * li), sqrtf(rr * rr + ri * ri));
    }
}

__device__ __forceinline__ void mma16816(float& d0, float& d1, float& d2, float& d3,
                                         unsigned a0, unsigned a1, unsigned a2, unsigned a3,
                                         unsigned b0, unsigned b1) {
    asm volatile(
        "mma.sync.aligned.m16n8k16.row.col.f32.f16.f16.f32 "
        "{%0,%1,%2,%3}, {%4,%5,%6,%7}, {%8,%9}, {%0,%1,%2,%3};"
        : "+f"(d0), "+f"(d1), "+f"(d2), "+f"(d3)
        : "r"(a0), "r"(a1), "r"(a2), "r"(a3), "r"(b0), "r"(b1));
}

// ---------------- persistent scan: all 19 steps, 2 batch rows per block ----------------
__global__ void __launch_bounds__(NTHR) k_steps(
        float* __restrict__ outYL, float* __restrict__ outYR, float* __restrict__ outQ,
        const float* __restrict__ w1, const float* __restrict__ b1,
        const float* __restrict__ g1, const float* __restrict__ be1,
        const float* __restrict__ w2, const float* __restrict__ b2,
        const float* __restrict__ g2, const float* __restrict__ be2,
        const float* __restrict__ w3, const float* __restrict__ b3) {
    __shared__ __align__(16) __half ahr[RPB][KTOT];     // per-row fp16 activations
    __shared__ __align__(16) float gs[RPB*GC];          // fp32 gate sums (from mma)
    __shared__ float2 magbuf[2][RPB*FFb];               // double-buffered magnitudes
    __shared__ float hold_s[RPB][128];
    __shared__ __align__(16) float hbuf[RPB][128];
    __shared__ __align__(16) float abuf[RPB][128];
    __shared__ float Qs[RPB][NBANDS];
    __shared__ float memLs[RPB][NBANDS], memRs[RPB][NBANDS];
    __shared__ float2 lnp[RPB][16];
    __shared__ float2 lnf[RPB];

    int tid = threadIdx.x, lane = tid & 31, wid = tid >> 5;
    int b0 = blockIdx.x * RPB;

    // thread mapping for 4-way split-K MLP phases
    int mrow = tid >> 9;
    int mo   = (tid >> 2) & 127;
    int mks  = tid & 3;

    // state init + t=0 mag load
    for (int i = tid; i < RPB*NBANDS; i += NTHR) {
        int r = i / NBANDS, n = i - r*NBANDS;
        Qs[r][n] = d_q0[n]; memLs[r][n] = 0.f; memRs[r][n] = 0.f;
    }
    for (int i = tid; i < RPB*KTOT; i += NTHR) ahr[i / KTOT][i % KTOT] = __float2half_rn(0.f);
    if (tid < RPB*128) hold_s[tid >> 7][tid & 127] = 0.f;
    for (int i = tid; i < RPB*FFb; i += NTHR) {
        int r = i / FFb, k = i - r*FFb;
        magbuf[0][i] = d_mag[(long long)((b0 + r)*TT + 0)*FFb + k];
    }
    __syncthreads();

    for (int t = 0; t < TT; t++) {
        const float2* magc = magbuf[t & 1];

        // ---- gammatone filterbank: warp per (row,band), Gaussian recurrence ----
        for (int task = wid; task < RPB*NBANDS; task += 32) {
            int r = task / NBANDS, n = task - r*NBANDS;
            const float2* mrow_p = magc + r*FFb;
            float Q  = Qs[r][n];
            float fc = d_fc[n];
            float bw = fc / (Q + 1e-8f) + 1e-8f;
            float inv = 1.0f / bw;
            float rad = 5.0f * bw;
            int kmin = (int)ceilf((fc - rad) * 0.064f);  if (kmin < 0)   kmin = 0;
            int kmax = (int)floorf((fc + rad) * 0.064f); if (kmax > 512) kmax = 512;
            float Dlt = 500.f * inv;
            float c1 = __expf(-0.5f * Dlt * Dlt);
            float c2 = c1 * c1;
            int k = kmin + lane;
            float d0 = ((float)k * 15.625f - fc) * inv;
            float w  = __expf(-0.5f * d0 * d0);
            float u  = __expf(-d0 * Dlt);
            float sw = 0.f, sl = 0.f, sr = 0.f;
            for (; k <= kmax; k += 32) {
                float2 m = mrow_p[k];
                sw += w; sl = fmaf(w, m.x, sl); sr = fmaf(w, m.y, sr);
                w = (w * c1) * u;
                u *= c2;
            }
#pragma unroll
            for (int off = 16; off; off >>= 1) {
                sw += __shfl_down_sync(0xffffffffu, sw, off);
                sl += __shfl_down_sync(0xffffffffu, sl, off);
                sr += __shfl_down_sync(0xffffffffu, sr, off);
            }
            if (lane == 0) {
                float den = 1.0f / (sw + 1e-8f);
                float yl = sl * den, yr = sr * den;
                long long oi = ((long long)(b0 + r)*TT + t)*NBANDS + n;
                outYL[oi] = yl; outYR[oi] = yr; outQ[oi] = Q;
                float cL = log1pf(fmaxf(yl, 0.f));
                float cR = log1pf(fmaxf(yr, 0.f));
                float mLo = memLs[r][n], mRo = memRs[r][n];
                ahr[r][n]       = __float2half_rn(cL);
                ahr[r][100 + n] = __float2half_rn(mLo);
                ahr[r][200 + n] = __float2half_rn(cR);
                ahr[r][300 + n] = __float2half_rn(mRo);
                memLs[r][n] = 0.8f * mLo + 0.2f * cL;
                memRs[r][n] = 0.8f * mRo + 0.2f * cR;
            }
        }
        __syncthreads();

        // ---- GRU GEMM via mma.sync: warp owns 16 gate columns, full K ----
        {
            float acc0[4] = {0.f, 0.f, 0.f, 0.f};
            float acc1[4] = {0.f, 0.f, 0.f, 0.f};
            const uint4* wp = ((const uint4*)d_Wb) + (wid*NKT)*32 + lane;
            int r = lane >> 2, q = lane & 3;
            bool alive = (lane < 8);
#pragma unroll 3
            for (int kt = 0; kt < NKT; kt++) {
                uint4 w4 = wp[kt * 32];
                unsigned a0 = 0, a2 = 0;
                if (alive) {
                    int kk = kt*16 + 2*q;
                    a0 = *(const unsigned*)&ahr[r][kk];
                    a2 = *(const unsigned*)&ahr[r][kk + 8];
                }
                mma16816(acc0[0], acc0[1], acc0[2], acc0[3], a0, 0u, a2, 0u, w4.x, w4.y);
                mma16816(acc1[0], acc1[1], acc1[2], acc1[3], a0, 0u, a2, 0u, w4.z, w4.w);
            }
            if (alive) {
                int cb = wid*16 + 2*q;
                *(float2*)&gs[r*GC + cb]     = make_float2(acc0[0], acc0[1]);
                *(float2*)&gs[r*GC + cb + 8] = make_float2(acc1[0], acc1[1]);
            }
        }
        __syncthreads();

        // ---- gating (256 threads) + next-step mag prefetch (other 768, looped) ----
        if (tid < RPB*128) {
            int row = tid >> 7, d = tid & 127;
            const float* g = &gs[row*GC];
            float gr  = g[d]       + d_biasc[d];
            float gz  = g[128 + d] + d_biasc[128 + d];
            float gin = g[256 + d] + d_biasc[256 + d];
            float ghn = g[384 + d] + d_biasc[384 + d];
            float rg = 1.f / (1.f + __expf(-gr));
            float zg = 1.f / (1.f + __expf(-gz));
            float ng = tanhf(gin + rg * ghn);
            float hn = (1.f - zg) * ng + zg * hold_s[row][d];
            hold_s[row][d] = hn;
            hbuf[row][d] = hn;
            ahr[row][400 + d] = __float2half_rn(hn);
        } else {
            int tn = (t + 1 < TT) ? t + 1 : t;
            for (int i = tid - RPB*128; i < RPB*FFb; i += NTHR - RPB*128) {
                int r = i / FFb, k = i - r*FFb;
                magbuf[(t + 1) & 1][i] = d_mag[(long long)((b0 + r)*TT + tn)*FFb + k];
            }
        }
        __syncthreads();

        // ---- MLP layer 1: v = hbuf @ w1^T (4-way split-K, all threads) ----
        float v1;
        {
            float acc = 0.f;
            const float* wr_ = w1 + mo*128 + mks*4;
#pragma unroll
            for (int j = 0; j < 8; j++) {
                float4 wv = *(const float4*)(wr_ + j*16);
                float4 hv = *(const float4*)&hbuf[mrow][j*16 + mks*4];
                acc += wv.x*hv.x + wv.y*hv.y + wv.z*hv.z + wv.w*hv.w;
            }
            acc += __shfl_xor_sync(0xffffffffu, acc, 1);
            acc += __shfl_xor_sync(0xffffffffu, acc, 2);
            v1 = acc + b1[mo];
            float s1 = v1, s2 = v1 * v1;
#pragma unroll
            for (int off = 16; off; off >>= 1) {
                s1 += __shfl_down_sync(0xffffffffu, s1, off);
                s2 += __shfl_down_sync(0xffffffffu, s2, off);
            }
            if (lane == 0) lnp[mrow][wid & 15] = make_float2(s1, s2);
        }
        __syncthreads();
        if (wid < RPB) {
            float s1 = 0.f, s2 = 0.f;
            if (lane < 16) { float2 p = lnp[wid][lane]; s1 = p.x; s2 = p.y; }
#pragma unroll
            for (int off = 8; off; off >>= 1) {
                s1 += __shfl_down_sync(0xffffffffu, s1, off);
                s2 += __shfl_down_sync(0xffffffffu, s2, off);
            }
            if (lane == 0) {
                float mean = s1 * (1.f/512.f);
                float var  = s2 * (1.f/512.f) - mean * mean;
                lnf[wid] = make_float2(mean, rsqrtf(var + 1e-5f));
            }
        }
        __syncthreads();
        if (mks == 0) {
            float2 f = lnf[mrow];
            float x = (v1 - f.x) * f.y * g1[mo] + be1[mo];
            abuf[mrow][mo] = x / (1.f + __expf(-x));
        }
        __syncthreads();

        // ---- MLP layer 2 ----
        float v2;
        {
            float acc = 0.f;
            const float* wr_ = w2 + mo*128 + mks*4;
#pragma unroll
            for (int j = 0; j < 8; j++) {
                float4 wv = *(const float4*)(wr_ + j*16);
                float4 hv = *(const float4*)&abuf[mrow][j*16 + mks*4];
                acc += wv.x*hv.x + wv.y*hv.y + wv.z*hv.z + wv.w*hv.w;
            }
            acc += __shfl_xor_sync(0xffffffffu, acc, 1);
            acc += __shfl_xor_sync(0xffffffffu, acc, 2);
            v2 = acc + b2[mo];
            float s1 = v2, s2 = v2 * v2;
#pragma unroll
            for (int off = 16; off; off >>= 1) {
                s1 += __shfl_down_sync(0xffffffffu, s1, off);
                s2 += __shfl_down_sync(0xffffffffu, s2, off);
            }
            if (lane == 0) lnp[mrow][wid & 15] = make_float2(s1, s2);
        }
        __syncthreads();
        if (wid < RPB) {
            float s1 = 0.f, s2 = 0.f;
            if (lane < 16) { float2 p = lnp[wid][lane]; s1 = p.x; s2 = p.y; }
#pragma unroll
            for (int off = 8; off; off >>= 1) {
                s1 += __shfl_down_sync(0xffffffffu, s1, off);
                s2 += __shfl_down_sync(0xffffffffu, s2, off);
            }
            if (lane == 0) {
                float mean = s1 * (1.f/512.f);
                float var  = s2 * (1.f/512.f) - mean * mean;
                lnf[wid] = make_float2(mean, rsqrtf(var + 1e-5f));
            }
        }
        __syncthreads();
        if (mks == 0) {
            float2 f = lnf[mrow];
            float x = (v2 - f.x) * f.y * g2[mo] + be2[mo];
            hbuf[mrow][mo] = x / (1.f + __expf(-x));
        }
        __syncthreads();

        // ---- head + Q update: 800 threads, 4-way split-K ----
        if (tid < 800) {
            int row = tid / 400;
            int rem = tid - row * 400;
            int o = rem >> 2, ks = rem & 3;
            float acc = 0.f;
            const float* wr_ = w3 + o*128 + ks*4;
#pragma unroll
            for (int j = 0; j < 8; j++) {
                float4 wv = *(const float4*)(wr_ + j*16);
                float4 hv = *(const float4*)&hbuf[row][j*16 + ks*4];
                acc += wv.x*hv.x + wv.y*hv.y + wv.z*hv.z + wv.w*hv.w;
            }
            acc += __shfl_xor_sync(0xffffffffu, acc, 1);
            acc += __shfl_xor_sync(0xffffffffu, acc, 2);
            if (ks == 0) {
                float delta = tanhf(acc + b3[o]);
                float qt = d_q0[o] + delta * d_dq[o];
                float qn = 0.8f * Qs[row][o] + 0.2f * qt;
                Qs[row][o] = fminf(fmaxf(qn, 0.05f), 30.f);
            }
        }
        __syncthreads();
    }
}

// ---------------- launch ----------------
extern "C" void kernel_launch(void* const* d_in, const int* in_sizes, int n_in,
                              void* d_out, int out_size) {
    const float* wavL = (const float*)d_in[0];
    const float* wavR = (const float*)d_in[1];
    const float* w_ih = (const float*)d_in[2];
    const float* w_hh = (const float*)d_in[3];
    const float* b_ih = (const float*)d_in[4];
    const float* b_hh = (const float*)d_in[5];
    const float* w1  = (const float*)d_in[6];
    const float* b1  = (const float*)d_in[7];
    const float* g1  = (const float*)d_in[8];
    const float* be1 = (const float*)d_in[9];
    const float* w2  = (const float*)d_in[10];
    const float* b2  = (const float*)d_in[11];
    const float* g2  = (const float*)d_in[12];
    const float* be2 = (const float*)d_in[13];
    const float* w3  = (const float*)d_in[14];
    const float* b3  = (const float*)d_in[15];

    long long out_elems = (long long)out_size;
    const long long NYQ = 3LL * BB * TT * NBANDS;       // 1,459,200
    const long long XSZ = (long long)BB * TT * FFb;     // 2,495,232 per X (real plane)
    int realmode = (out_elems < NYQ + 3 * XSZ) ? 1 : 0;

    float* out = (float*)d_out;
    float* outYL = out;
    float* outYR = outYL + (long long)BB * TT * NBANDS;
    float* outQ  = outYR + (long long)BB * TT * NBANDS;
    long long xl_off = NYQ;
    long long xr_off = realmode ? (NYQ + XSZ) : (NYQ + 2 * XSZ);
    float* outXL = out + xl_off;
    float* outXR = out + xr_off;

    const int PREP_N = WB_UINTS + GC;
    k_consts<<<1, 128>>>();
    k_prep<<<(PREP_N + 255) / 256, 256>>>(w_ih, w_hh, b_ih, b_hh);
    k_fft<<<BB * TT, 256>>>(wavL, wavR, outXL, outXR, realmode, xl_off, xr_off, out_elems);
    k_steps<<<NBLK, NTHR>>>(outYL, outYR, outQ,
                            w1, b1, g1, be1, w2, b2, g2, be2, w3, b3);
}

// round 15
// speedup vs baseline: 1.1970x; 1.1970x over previous
#include <cuda_runtime.h>
#include <cuda_fp16.h>

#define NBANDS 100
#define TT 19
#define FFb 513
#define BB 256
#define KTOT 528          // 400 feat + 128 h (= 33 k-tiles of 16)
#define GC 512            // gate columns: rz(256) | i_n(128) | h_n(128)
#define WINLEN 842
#define FSAMP 16000
#define RPB 2             // batch rows per block
#define NBLK (BB/RPB)     // 128 blocks
#define NTHR 1024
#define NKT 33            // k-tiles (GRU)
#define WB_UINTS (32*NKT*32*4)   // GRU B-fragment weights, 135168 uints
#define M1_U2 (16*8*32)          // MLP1 frag uint2 count (4096)
#define M2_U2 (16*8*32)
#define M3_U2 (13*8*32)          // head (104 cols, 100 used)

// ---------------- device state / scratch ----------------
__device__ float d_fc[NBANDS], d_q0[NBANDS], d_dq[NBANDS];
__device__ __align__(16) unsigned d_Wb[WB_UINTS];  // GRU mma B-frags
__device__ __align__(16) uint2 d_Wm1[M1_U2];       // MLP1 B-frags (fp16)
__device__ __align__(16) uint2 d_Wm2[M2_U2];
__device__ __align__(16) uint2 d_Wm3[M3_U2];
__device__ float d_biasc[GC];
__device__ __align__(16) float2 d_mag[BB*TT*FFb];  // (|L|,|R|)

// ---------------- constants (ERB scale) ----------------
__global__ void k_consts() {
    int n = threadIdx.x;
    if (n < NBANDS) {
        double E0 = 21.4 * log10(4.37 * 50.0   / 1000.0 + 1.0);
        double E1 = 21.4 * log10(4.37 * 7200.0 / 1000.0 + 1.0);
        double E  = E0 + (E1 - E0) * ((double)n / 99.0);
        double fc = (pow(10.0, E / 21.4) - 1.0) * 1000.0 / 4.37;
        double erb = 24.7 * (4.37 * fc / 1000.0 + 1.0);
        double q0 = fc / (1.019 * erb);
        double En = (E - E0) / (E1 - E0 + 1e-12);
        double dq = 2.0 * (0.5 + 0.5 * En);
        if (dq < 0.001) dq = 0.001;
        d_fc[n] = (float)fc; d_q0[n] = (float)q0; d_dq[n] = (float)dq;
    }
}

__device__ __forceinline__ float wcomb(const float* w_ih, const float* w_hh, int col, int k) {
    if (k >= KTOT) return 0.f;
    if (col < 256) return (k < 400) ? w_ih[col*400 + k] : w_hh[col*128 + (k-400)];
    if (col < 384) return (k < 400) ? w_ih[col*400 + k] : 0.f;
    return (k < 400) ? 0.f : w_hh[(col-128)*128 + (k-400)];
}

// Pack one MLP fragment element: e -> (w,kt,lane); W is [Nout][128] row-major.
__device__ __forceinline__ uint2 pack_mlp(const float* W, int Nout, int e) {
    int lane = e & 31, kt = (e >> 5) & 7, w = e >> 8;
    int n  = w*8 + (lane >> 2);
    int kb = kt*16 + (lane & 3)*2;
    float a0 = 0.f, a1 = 0.f, a2 = 0.f, a3 = 0.f;
    if (n < Nout) {
        a0 = W[n*128 + kb];     a1 = W[n*128 + kb + 1];
        a2 = W[n*128 + kb + 8]; a3 = W[n*128 + kb + 9];
    }
    __half2 h0 = __floats2half2_rn(a0, a1);
    __half2 h1 = __floats2half2_rn(a2, a3);
    uint2 r; r.x = *(unsigned*)&h0; r.y = *(unsigned*)&h1;
    return r;
}

// Build all fragment-packed weights + GRU bias
__global__ void k_prep(const float* __restrict__ w_ih, const float* __restrict__ w_hh,
                       const float* __restrict__ b_ih, const float* __restrict__ b_hh,
                       const float* __restrict__ w1, const float* __restrict__ w2,
                       const float* __restrict__ w3) {
    int i = blockIdx.x * blockDim.x + threadIdx.x;
    if (i < WB_UINTS) {
        int tmp = i;
        int j    = tmp & 3;  tmp >>= 2;
        int lane = tmp & 31; tmp >>= 5;
        int kt   = tmp % NKT;
        int warp = tmp / NKT;
        int ntile = j >> 1, reg = j & 1;
        int n  = warp*16 + ntile*8 + (lane >> 2);
        int kb = kt*16 + (lane & 3)*2 + reg*8;
        float v0 = wcomb(w_ih, w_hh, n, kb);
        float v1 = wcomb(w_ih, w_hh, n, kb + 1);
        __half2 h = __floats2half2_rn(v0, v1);
        d_Wb[i] = *(unsigned*)&h;
        return;
    }
    int j = i - WB_UINTS;
    if (j < GC) {
        float v;
        if (j < 256)      v = b_ih[j] + b_hh[j];
        else if (j < 384) v = b_ih[j];
        else              v = b_hh[j - 128];
        d_biasc[j] = v;
        return;
    }
    j -= GC;
    if (j < M1_U2) { d_Wm1[j] = pack_mlp(w1, 128, j); return; }
    j -= M1_U2;
    if (j < M2_U2) { d_Wm2[j] = pack_mlp(w2, 128, j); return; }
    j -= M2_U2;
    if (j < M3_U2) { d_Wm3[j] = pack_mlp(w3, 100, j); }
}

// ---------------- packed L+iR 1024-pt FFT per (b,t), smem twiddles ----------------
__global__ void k_fft(const float* __restrict__ wavL, const float* __restrict__ wavR,
                      float* __restrict__ outXL, float* __restrict__ outXR,
                      int realmode, long long xl_off, long long xr_off, long long out_elems) {
    __shared__ float2 z[1024];
    __shared__ float2 twt[1023];
    int bt = blockIdx.x;
    int b = bt / TT, t = bt - b * TT;
    int tid = threadIdx.x;
    const float* wl = wavL + b * FSAMP + t * WINLEN;
    const float* wr = wavR + b * FSAMP + t * WINLEN;

    for (int g = tid; g < 1023; g += 256) {
        int hb = 31 - __clz(g + 1);
        int half = 1 << hb;
        int j = g + 1 - half;
        float s, c;
        __sincosf(-3.14159265358979f * (float)j / (float)half, &s, &c);
        twt[g] = make_float2(c, s);
    }
    for (int j = tid; j < 1024; j += 256) {
        float2 v = make_float2(0.f, 0.f);
        if (j < WINLEN) {
            float w = 0.5f - 0.5f * cosf(6.2831853071795864f * (float)j / (float)WINLEN);
            v.x = wl[j] * w; v.y = wr[j] * w;
        }
        z[__brev((unsigned)j) >> 22] = v;
    }
    __syncthreads();

    for (int len = 2; len <= 1024; len <<= 1) {
        int half = len >> 1;
        for (int i = tid; i < 512; i += 256) {
            int j = i & (half - 1);
            int base = ((i - j) << 1) + j;
            float2 w2 = twt[half - 1 + j];
            float c = w2.x, s = w2.y;
            float2 u = z[base], v = z[base + half];
            float tr = v.x * c - v.y * s;
            float ti = v.x * s + v.y * c;
            z[base]        = make_float2(u.x + tr, u.y + ti);
            z[base + half] = make_float2(u.x - tr, u.y - ti);
        }
        __syncthreads();
    }

    for (int k = tid; k < FFb; k += 256) {
        float2 zk = z[k];
        float2 zm = z[(1024 - k) & 1023];
        float lr = 0.5f * (zk.x + zm.x), li = 0.5f * (zk.y - zm.y);
        float rr = 0.5f * (zk.y + zm.y), ri = 0.5f * (zm.x - zk.x);
        long long o = (long long)bt * FFb + k;
        if (realmode) {
            outXL[o] = lr;
            outXR[o] = rr;
        } else {
            long long base2 = o * 2;
            if (xl_off + base2 + 1 < out_elems) {
                outXL[base2] = lr; outXL[base2 + 1] = li;
            }
            if (xr_off + base2 + 1 < out_elems) {
                outXR[base2] = rr; outXR[base2 + 1] = ri;
            }
        }
        d_mag[o] = make_float2(sqrtf(lr * lr + li * li), sqrtf(rr * rr + ri * ri));
    }
}

__device__ __forceinline__ void mma16816(float& d0, float& d1, float& d2, float& d3,
                                         unsigned a0, unsigned a1, unsigned a2, unsigned a3,
                                         unsigned b0, unsigned b1) {
    asm volatile(
        "mma.sync.aligned.m16n8k16.row.col.f32.f16.f16.f32 "
        "{%0,%1,%2,%3}, {%4,%5,%6,%7}, {%8,%9}, {%0,%1,%2,%3};"
        : "+f"(d0), "+f"(d1), "+f"(d2), "+f"(d3)
        : "r"(a0), "r"(a1), "r"(a2), "r"(a3), "r"(b0), "r"(b1));
}

// 8-ktile (K=128) mma chain; A row-contiguous fp16 with stride AS elements.
// Returns (c0,c1): v for row lane>>2 (lanes 0..7), cols ntile*8 + 2*(lane&3) (+1).
__device__ __forceinline__ float2 mlp_mma8(const uint2* __restrict__ wf,
                                           const __half* __restrict__ A, int AS, int lane) {
    float d0 = 0.f, d1 = 0.f, d2 = 0.f, d3 = 0.f;
    int r = lane >> 2, q = lane & 3;
    bool alive = (lane < 8);
#pragma unroll
    for (int kt = 0; kt < 8; kt++) {
        uint2 b = wf[kt*32 + lane];
        unsigned x0 = 0, x2 = 0;
        if (alive) {
            int kk = kt*16 + 2*q;
            x0 = *(const unsigned*)&A[r*AS + kk];
            x2 = *(const unsigned*)&A[r*AS + kk + 8];
        }
        mma16816(d0, d1, d2, d3, x0, 0u, x2, 0u, b.x, b.y);
    }
    return make_float2(d0, d1);
}

// ---------------- persistent scan: all 19 steps, 2 batch rows per block ----------------
__global__ void __launch_bounds__(NTHR) k_steps(
        float* __restrict__ outYL, float* __restrict__ outYR, float* __restrict__ outQ,
        const float* __restrict__ b1, const float* __restrict__ g1, const float* __restrict__ be1,
        const float* __restrict__ b2, const float* __restrict__ g2, const float* __restrict__ be2,
        const float* __restrict__ b3) {
    __shared__ __align__(16) __half ahr[RPB][KTOT];     // per-row fp16 activations (feat|h)
    __shared__ __align__(16) __half am1[RPB][128];      // MLP layer outputs fp16
    __shared__ __align__(16) __half am2[RPB][128];
    __shared__ __align__(16) float gs[RPB*GC];          // fp32 gate sums (GRU mma)
    __shared__ float2 magbuf[2][RPB*FFb];               // double-buffered magnitudes
    __shared__ float hold_s[RPB][128];
    __shared__ float Qs[RPB][NBANDS];
    __shared__ float memLs[RPB][NBANDS], memRs[RPB][NBANDS];
    __shared__ float2 lnp[RPB][16];
    __shared__ float2 lnf[RPB];

    int tid = threadIdx.x, lane = tid & 31, wid = tid >> 5;
    int b0 = blockIdx.x * RPB;

    // state init + t=0 mag load
    for (int i = tid; i < RPB*NBANDS; i += NTHR) {
        int r = i / NBANDS, n = i - r*NBANDS;
        Qs[r][n] = d_q0[n]; memLs[r][n] = 0.f; memRs[r][n] = 0.f;
    }
    for (int i = tid; i < RPB*KTOT; i += NTHR) ahr[i / KTOT][i % KTOT] = __float2half_rn(0.f);
    if (tid < RPB*128) hold_s[tid >> 7][tid & 127] = 0.f;
    for (int i = tid; i < RPB*FFb; i += NTHR) {
        int r = i / FFb, k = i - r*FFb;
        magbuf[0][i] = d_mag[(long long)((b0 + r)*TT + 0)*FFb + k];
    }
    __syncthreads();

    for (int t = 0; t < TT; t++) {
        const float2* magc = magbuf[t & 1];

        // ---- gammatone filterbank: warp per (row,band), Gaussian recurrence ----
        for (int task = wid; task < RPB*NBANDS; task += 32) {
            int r = task / NBANDS, n = task - r*NBANDS;
            const float2* mrow_p = magc + r*FFb;
            float Q  = Qs[r][n];
            float fc = d_fc[n];
            float bw = fc / (Q + 1e-8f) + 1e-8f;
            float inv = 1.0f / bw;
            float rad = 5.0f * bw;
            int kmin = (int)ceilf((fc - rad) * 0.064f);  if (kmin < 0)   kmin = 0;
            int kmax = (int)floorf((fc + rad) * 0.064f); if (kmax > 512) kmax = 512;
            float Dlt = 500.f * inv;
            float c1 = __expf(-0.5f * Dlt * Dlt);
            float c2 = c1 * c1;
            int k = kmin + lane;
            float d0 = ((float)k * 15.625f - fc) * inv;
            float w  = __expf(-0.5f * d0 * d0);
            float u  = __expf(-d0 * Dlt);
            float sw = 0.f, sl = 0.f, sr = 0.f;
            for (; k <= kmax; k += 32) {
                float2 m = mrow_p[k];
                sw += w; sl = fmaf(w, m.x, sl); sr = fmaf(w, m.y, sr);
                w = (w * c1) * u;
                u *= c2;
            }
#pragma unroll
            for (int off = 16; off; off >>= 1) {
                sw += __shfl_down_sync(0xffffffffu, sw, off);
                sl += __shfl_down_sync(0xffffffffu, sl, off);
                sr += __shfl_down_sync(0xffffffffu, sr, off);
            }
            if (lane == 0) {
                float den = 1.0f / (sw + 1e-8f);
                float yl = sl * den, yr = sr * den;
                long long oi = ((long long)(b0 + r)*TT + t)*NBANDS + n;
                outYL[oi] = yl; outYR[oi] = yr; outQ[oi] = Q;
                float cL = log1pf(fmaxf(yl, 0.f));
                float cR = log1pf(fmaxf(yr, 0.f));
                float mLo = memLs[r][n], mRo = memRs[r][n];
                ahr[r][n]       = __float2half_rn(cL);
                ahr[r][100 + n] = __float2half_rn(mLo);
                ahr[r][200 + n] = __float2half_rn(cR);
                ahr[r][300 + n] = __float2half_rn(mRo);
                memLs[r][n] = 0.8f * mLo + 0.2f * cL;
                memRs[r][n] = 0.8f * mRo + 0.2f * cR;
            }
        }
        __syncthreads();

        // ---- GRU GEMM via mma.sync: warp owns 16 gate columns, full K ----
        {
            float acc0[4] = {0.f, 0.f, 0.f, 0.f};
            float acc1[4] = {0.f, 0.f, 0.f, 0.f};
            const uint4* wp = ((const uint4*)d_Wb) + (wid*NKT)*32 + lane;
            int r = lane >> 2, q = lane & 3;
            bool alive = (lane < 8);
#pragma unroll 3
            for (int kt = 0; kt < NKT; kt++) {
                uint4 w4 = wp[(size_t)kt * 32];
                unsigned a0 = 0, a2 = 0;
                if (alive) {
                    int kk = kt*16 + 2*q;
                    a0 = *(const unsigned*)&ahr[r][kk];
                    a2 = *(const unsigned*)&ahr[r][kk + 8];
                }
                mma16816(acc0[0], acc0[1], acc0[2], acc0[3], a0, 0u, a2, 0u, w4.x, w4.y);
                mma16816(acc1[0], acc1[1], acc1[2], acc1[3], a0, 0u, a2, 0u, w4.z, w4.w);
            }
            if (alive) {
                int cb = wid*16 + 2*q;
                *(float2*)&gs[r*GC + cb]     = make_float2(acc0[0], acc0[1]);
                *(float2*)&gs[r*GC + cb + 8] = make_float2(acc1[0], acc1[1]);
            }
        }
        __syncthreads();

        // ---- gating (256 threads) + next-step mag prefetch (other 768, looped) ----
        if (tid < RPB*128) {
            int row = tid >> 7, d = tid & 127;
            const float* g = &gs[row*GC];
            float gr  = g[d]       + d_biasc[d];
            float gz  = g[128 + d] + d_biasc[128 + d];
            float gin = g[256 + d] + d_biasc[256 + d];
            float ghn = g[384 + d] + d_biasc[384 + d];
            float rg = 1.f / (1.f + __expf(-gr));
            float zg = 1.f / (1.f + __expf(-gz));
            float ng = tanhf(gin + rg * ghn);
            float hn = (1.f - zg) * ng + zg * hold_s[row][d];
            hold_s[row][d] = hn;
            ahr[row][400 + d] = __float2half_rn(hn);
        } else {
            int tn = (t + 1 < TT) ? t + 1 : t;
            for (int i = tid - RPB*128; i < RPB*FFb; i += NTHR - RPB*128) {
                int r = i / FFb, k = i - r*FFb;
                magbuf[(t + 1) & 1][i] = d_mag[(long long)((b0 + r)*TT + tn)*FFb + k];
            }
        }
        __syncthreads();

        // ---- MLP layer 1 via mma: 16 warps, 8 outputs each ----
        float v1a = 0.f, v1b = 0.f;
        {
            if (wid < 16) {
                float2 v = mlp_mma8(d_Wm1 + wid*8*32, &ahr[0][400], KTOT, lane);
                int c = wid*8 + 2*(lane & 3);
                v1a = v.x + b1[c]; v1b = v.y + b1[c + 1];
                float s1 = v1a + v1b, s2 = v1a*v1a + v1b*v1b;
                s1 += __shfl_xor_sync(0xffffffffu, s1, 1); s1 += __shfl_xor_sync(0xffffffffu, s1, 2);
                s2 += __shfl_xor_sync(0xffffffffu, s2, 1); s2 += __shfl_xor_sync(0xffffffffu, s2, 2);
                if ((lane & 3) == 0 && lane < 8) lnp[lane >> 2][wid] = make_float2(s1, s2);
            }
        }
        __syncthreads();
        if (wid < RPB) {
            float s1 = 0.f, s2 = 0.f;
            if (lane < 16) { float2 p = lnp[wid][lane]; s1 = p.x; s2 = p.y; }
#pragma unroll
            for (int off = 8; off; off >>= 1) {
                s1 += __shfl_down_sync(0xffffffffu, s1, off);
                s2 += __shfl_down_sync(0xffffffffu, s2, off);
            }
            if (lane == 0) {
                float mean = s1 * (1.f/128.f);
                float var  = s2 * (1.f/128.f) - mean * mean;
                lnf[wid] = make_float2(mean, rsqrtf(var + 1e-5f));
            }
        }
        __syncthreads();
        if (wid < 16 && lane < 8) {
            int r = lane >> 2, c = wid*8 + 2*(lane & 3);
            float2 f = lnf[r];
            float x0 = (v1a - f.x) * f.y * g1[c]     + be1[c];
            float x1 = (v1b - f.x) * f.y * g1[c + 1] + be1[c + 1];
            am1[r][c]     = __float2half_rn(x0 / (1.f + __expf(-x0)));
            am1[r][c + 1] = __float2half_rn(x1 / (1.f + __expf(-x1)));
        }
        __syncthreads();

        // ---- MLP layer 2 via mma ----
        float v2a = 0.f, v2b = 0.f;
        {
            if (wid < 16) {
                float2 v = mlp_mma8(d_Wm2 + wid*8*32, &am1[0][0], 128, lane);
                int c = wid*8 + 2*(lane & 3);
                v2a = v.x + b2[c]; v2b = v.y + b2[c + 1];
                float s1 = v2a + v2b, s2 = v2a*v2a + v2b*v2b;
                s1 += __shfl_xor_sync(0xffffffffu, s1, 1); s1 += __shfl_xor_sync(0xffffffffu, s1, 2);
                s2 += __shfl_xor_sync(0xffffffffu, s2, 1); s2 += __shfl_xor_sync(0xffffffffu, s2, 2);
                if ((lane & 3) == 0 && lane < 8) lnp[lane >> 2][wid] = make_float2(s1, s2);
            }
        }
        __syncthreads();
        if (wid < RPB) {
            float s1 = 0.f, s2 = 0.f;
            if (lane < 16) { float2 p = lnp[wid][lane]; s1 = p.x; s2 = p.y; }
#pragma unroll
            for (int off = 8; off; off >>= 1) {
                s1 += __shfl_down_sync(0xffffffffu, s1, off);
                s2 += __shfl_down_sync(0xffffffffu, s2, off);
            }
            if (lane == 0) {
                float mean = s1 * (1.f/128.f);
                float var  = s2 * (1.f/128.f) - mean * mean;
                lnf[wid] = make_float2(mean, rsqrtf(var + 1e-5f));
            }
        }
        __syncthreads();
        if (wid < 16 && lane < 8) {
            int r = lane >> 2, c = wid*8 + 2*(lane & 3);
            float2 f = lnf[r];
            float x0 = (v2a - f.x) * f.y * g2[c]     + be2[c];
            float x1 = (v2b - f.x) * f.y * g2[c + 1] + be2[c + 1];
            am2[r][c]     = __float2half_rn(x0 / (1.f + __expf(-x0)));
            am2[r][c + 1] = __float2half_rn(x1 / (1.f + __expf(-x1)));
        }
        __syncthreads();

        // ---- head + Q update via mma: 13 warps, 8 outputs each ----
        if (wid < 13) {
            float2 v = mlp_mma8(d_Wm3 + wid*8*32, &am2[0][0], 128, lane);
            if (lane < 8) {
                int r = lane >> 2, c = wid*8 + 2*(lane & 3);
                if (c < NBANDS) {
                    float delta = tanhf(v.x + b3[c]);
                    float qt = d_q0[c] + delta * d_dq[c];
                    float qn = 0.8f * Qs[r][c] + 0.2f * qt;
                    Qs[r][c] = fminf(fmaxf(qn, 0.05f), 30.f);
                }
                if (c + 1 < NBANDS) {
                    float delta = tanhf(v.y + b3[c + 1]);
                    float qt = d_q0[c + 1] + delta * d_dq[c + 1];
                    float qn = 0.8f * Qs[r][c + 1] + 0.2f * qt;
                    Qs[r][c + 1] = fminf(fmaxf(qn, 0.05f), 30.f);
                }
            }
        }
        __syncthreads();
    }
}

// ---------------- launch ----------------
extern "C" void kernel_launch(void* const* d_in, const int* in_sizes, int n_in,
                              void* d_out, int out_size) {
    const float* wavL = (const float*)d_in[0];
    const float* wavR = (const float*)d_in[1];
    const float* w_ih = (const float*)d_in[2];
    const float* w_hh = (const float*)d_in[3];
    const float* b_ih = (const float*)d_in[4];
    const float* b_hh = (const float*)d_in[5];
    const float* w1  = (const float*)d_in[6];
    const float* b1  = (const float*)d_in[7];
    const float* g1  = (const float*)d_in[8];
    const float* be1 = (const float*)d_in[9];
    const float* w2  = (const float*)d_in[10];
    const float* b2  = (const float*)d_in[11];
    const float* g2  = (const float*)d_in[12];
    const float* be2 = (const float*)d_in[13];
    const float* w3  = (const float*)d_in[14];
    const float* b3  = (const float*)d_in[15];

    long long out_elems = (long long)out_size;
    const long long NYQ = 3LL * BB * TT * NBANDS;       // 1,459,200
    const long long XSZ = (long long)BB * TT * FFb;     // 2,495,232 per X (real plane)
    int realmode = (out_elems < NYQ + 3 * XSZ) ? 1 : 0;

    float* out = (float*)d_out;
    float* outYL = out;
    float* outYR = outYL + (long long)BB * TT * NBANDS;
    float* outQ  = outYR + (long long)BB * TT * NBANDS;
    long long xl_off = NYQ;
    long long xr_off = realmode ? (NYQ + XSZ) : (NYQ + 2 * XSZ);
    float* outXL = out + xl_off;
    float* outXR = out + xr_off;

    const int PREP_N = WB_UINTS + GC + M1_U2 + M2_U2 + M3_U2;
    k_consts<<<1, 128>>>();
    k_prep<<<(PREP_N + 255) / 256, 256>>>(w_ih, w_hh, b_ih, b_hh, w1, w2, w3);
    k_fft<<<BB * TT, 256>>>(wavL, wavR, outXL, outXR, realmode, xl_off, xr_off, out_elems);
    k_steps<<<NBLK, NTHR>>>(outYL, outYR, outQ,
                            b1, g1, be1, b2, g2, be2, b3);
}